// round 16
// baseline (speedup 1.0000x reference)
#include <cuda_runtime.h>
#include <cuda_fp16.h>
#include <math.h>
#include <stdint.h>

// Problem constants
#define BATCH 256
#define HID   768
#define G4    3072
#define TLEN  100
#define OUTD  72
#define SRCL  16
#define BH    (BATCH * HID)

// t=0 kernel geometry (per-launch, streams W0)
#define STAGE_K   64
#define A_TILEB   8192
#define W_TILEB   8192
#define BUFB      (A_TILEB + W_TILEB)
#define GSTRIDE   68
#define DYN_SMEM  (1024 + 2 * BUFB)

// persistent kernel geometry (t=1..99): W resident in smem
#define PNB        96                       // 48 nt x 2 mt CTAs (wave-1 co-resident)
#define W_SLAB     (24 * 8192)              // 24 chunks x (64 rows x 128B) = 192KB
#define A_ITEMB    16384                    // 128 rows x 128B per A item
#define P_SMEM     (1024 + W_SLAB + 2 * A_ITEMB)   // 230400 B <= 232448 max

// -------- device scratch (allocation-free: __device__ globals) --------
static __device__ __half g_Wr [G4 * 1536];      // rec W (Wih+Whh): row n -> [wh(768)|wl(768)]
static __device__ __half g_W0 [G4 * 3072];      // t=0 W [Wih|Whh]: row n -> [w0h|w0l]
static __device__ __half g_A0b[BATCH * 3072];   // [a0h|a0l], a0=[x0|h0]
static __device__ __half g_Ab [2][BATCH * 1536];// h hi/lo ping-pong
static __device__ float g_C[BATCH * HID];
static __device__ float g_H[TLEN * BATCH * HID];
static __device__ float g_biasPk[G4];           // bias, packed n = j*4 + g
static __device__ unsigned g_barA;              // grid barrier arrive counter
static __device__ volatile unsigned g_barR;     // grid barrier release generation

// -------- helpers --------
__device__ __forceinline__ uint32_t smem_u32(const void* p) {
    uint32_t a;
    asm("{ .reg .u64 t; cvta.to.shared.u64 t, %1; cvt.u32.u64 %0, t; }" : "=r"(a) : "l"(p));
    return a;
}
#define SWZ128(o) ((o) ^ (((o) >> 3) & 0x70))

__device__ __forceinline__ float sigmoidf_(float x) { return 1.0f / (1.0f + expf(-x)); }

__device__ __forceinline__ void cp_async16(uint32_t dst, const void* src) {
    asm volatile("cp.async.cg.shared.global [%0], [%1], 16;" :: "r"(dst), "l"(src));
}
#define CP_COMMIT()  asm volatile("cp.async.commit_group;" ::: "memory")
#define CP_WAIT(n)   asm volatile("cp.async.wait_group %0;" :: "n"(n) : "memory")

__device__ __forceinline__ void ldsm4(uint32_t* r, uint32_t addr) {
    asm volatile("ldmatrix.sync.aligned.m8n8.x4.shared.b16 {%0,%1,%2,%3}, [%4];"
                 : "=r"(r[0]), "=r"(r[1]), "=r"(r[2]), "=r"(r[3]) : "r"(addr));
}
__device__ __forceinline__ void mma16816(float* c, const uint32_t* a, const uint32_t* b) {
    asm volatile("mma.sync.aligned.m16n8k16.row.col.f32.f16.f16.f32 "
                 "{%0,%1,%2,%3}, {%4,%5,%6,%7}, {%8,%9}, {%0,%1,%2,%3};"
                 : "+f"(c[0]), "+f"(c[1]), "+f"(c[2]), "+f"(c[3])
                 : "r"(a[0]), "r"(a[1]), "r"(a[2]), "r"(a[3]), "r"(b[0]), "r"(b[1]));
}

// f32x2 helpers (post_proj)
__device__ __forceinline__ unsigned long long pack2(float x, float y) {
    unsigned long long r; asm("mov.b64 %0, {%1, %2};" : "=l"(r) : "f"(x), "f"(y)); return r;
}
__device__ __forceinline__ void unpack2(unsigned long long v, float& x, float& y) {
    asm("mov.b64 {%0, %1}, %2;" : "=f"(x), "=f"(y) : "l"(v));
}
__device__ __forceinline__ void fma2(unsigned long long& d, unsigned long long a, unsigned long long b) {
    asm("fma.rn.f32x2 %0, %1, %2, %0;" : "+l"(d) : "l"(a), "l"(b));
}

// packed-N index n = j*4 + g -> original weight row g*768 + j
__device__ __forceinline__ int rowFromN(int n) {
    return (n & 3) * HID + (n >> 2);
}

// ====================================================================
// Prep kernels
// ====================================================================
__global__ void prepWr(const float* __restrict__ Wih, const float* __restrict__ Whh) {
    const int stride = gridDim.x * blockDim.x;
    for (int idx = blockIdx.x * blockDim.x + threadIdx.x; idx < G4 * HID; idx += stride) {
        int n = idx / HID, k = idx - n * HID;
        int row = rowFromN(n);
        float w = Wih[row * HID + k] + Whh[row * HID + k];
        __half wh = __float2half_rn(w);
        g_Wr[n * 1536 + k]       = wh;
        g_Wr[n * 1536 + 768 + k] = __float2half_rn(w - __half2float(wh));
    }
}
__global__ void prepW0k(const float* __restrict__ Wih, const float* __restrict__ Whh) {
    const int stride = gridDim.x * blockDim.x;
    for (int idx = blockIdx.x * blockDim.x + threadIdx.x; idx < G4 * 1536; idx += stride) {
        int n = idx / 1536, k = idx - n * 1536;
        int row = rowFromN(n);
        float w = (k < HID) ? Wih[row * HID + k] : Whh[row * HID + (k - HID)];
        __half wh = __float2half_rn(w);
        g_W0[n * 3072 + k]        = wh;
        g_W0[n * 3072 + 1536 + k] = __float2half_rn(w - __half2float(wh));
    }
}
__global__ void prepState(const float* __restrict__ src, const float* __restrict__ h0,
                          const float* __restrict__ c0, const float* __restrict__ bih,
                          const float* __restrict__ bhh) {
    const int stride = gridDim.x * blockDim.x;
    const int t0 = blockIdx.x * blockDim.x + threadIdx.x;
    if (t0 == 0) { g_barA = 0; g_barR = 0; }     // reset grid barrier each replay
    for (int idx = t0; idx < BATCH * 1536; idx += stride) {
        int m = idx / 1536, q = idx - m * 1536;
        float a = (q < HID) ? src[(m * SRCL + (SRCL - 1)) * HID + q] : h0[m * HID + (q - HID)];
        __half ah = __float2half_rn(a);
        g_A0b[m * 3072 + q]        = ah;
        g_A0b[m * 3072 + 1536 + q] = __float2half_rn(a - __half2float(ah));
    }
    for (int idx = t0; idx < BATCH * HID; idx += stride) g_C[idx] = c0[idx];
    for (int idx = t0; idx < G4; idx += stride) {
        int row = rowFromN(idx);
        g_biasPk[idx] = bih[row] + bhh[row];
    }
}

// ====================================================================
// t=0 LSTM step (per-launch; streams W0). Grid (48,4), 128 thr. (R14 kernel)
// ====================================================================
__global__ __launch_bounds__(128) void lstm_step_mma(int t) {
    extern __shared__ char dyn_raw[];
    char* smb = (char*)(((uintptr_t)dyn_raw + 1023) & ~(uintptr_t)1023);

    const int tid  = threadIdx.x;
    const int wid  = tid >> 5;
    const int lane = tid & 31;
    const int nt   = blockIdx.x;
    const int m0   = blockIdx.y * 64;
    const int n0   = nt * 64;

    const __half* Aglob; const __half* Wglob; int kBase;
    if (t == 0) { Aglob = g_A0b; Wglob = g_W0; kBase = 1536; }
    else        { Aglob = g_Ab[t & 1]; Wglob = g_Wr; kBase = 768; }
    const int rowStride = 2 * kBase;
    const int nStages   = (3 * kBase) / STAGE_K;

    const int mwOff = (wid & 1) * 32;
    const int nwOff = (wid >> 1) * 32;
    const int frow = tid >> 3;
    const int fcb  = (tid & 7) * 16;
    const int grp = lane >> 3, lrw = lane & 7;
    const int aRow = ((grp & 1) ? 8 : 0) + lrw;
    const int aKx  = (grp & 2) ? 16 : 0;
    const int bRow = ((grp & 2) ? 8 : 0) + lrw;
    const int bKx  = (grp & 1) ? 16 : 0;

    const uint32_t smb32 = smem_u32(smb);

    float acc[2][4][4];
#pragma unroll
    for (int a = 0; a < 2; a++)
#pragma unroll
        for (int b = 0; b < 4; b++)
#pragma unroll
            for (int c = 0; c < 4; c++) acc[a][b][c] = 0.0f;

    auto fill = [&](int s) {
        const int b = s & 1;
        const uint32_t dA = smb32 + b * BUFB;
        const uint32_t dW = dA + A_TILEB;
        const int segBase = s * STAGE_K;
        const int seg = segBase / kBase;
        const int kk  = segBase - seg * kBase;
        const int aOff = (seg == 1) ? kBase + kk : kk;
        const int wOff = (seg == 2) ? kBase + kk : kk;
#pragma unroll
        for (int i = 0; i < 4; i++) {
            int row = frow + 16 * i;
            cp_async16(dA + SWZ128(row * 128 + fcb),
                       (const char*)Aglob + ((size_t)(m0 + row) * rowStride + aOff) * 2 + fcb);
        }
#pragma unroll
        for (int i = 0; i < 4; i++) {
            int row = frow + 16 * i;
            cp_async16(dW + SWZ128(row * 128 + fcb),
                       (const char*)Wglob + ((size_t)(n0 + row) * rowStride + wOff) * 2 + fcb);
        }
    };

    fill(0); CP_COMMIT();

    for (int s = 0; s < nStages; s++) {
        if (s + 1 < nStages) { fill(s + 1); CP_COMMIT(); CP_WAIT(1); }
        else                 { CP_WAIT(0); }
        __syncthreads();

        const uint32_t bA = smb32 + (s & 1) * BUFB;
        const uint32_t bW = bA + A_TILEB;
#pragma unroll
        for (int k16 = 0; k16 < 4; k16++) {
            const int kb = k16 * 32;
            uint32_t af[2][4];
#pragma unroll
            for (int mf = 0; mf < 2; mf++) {
                int row = mwOff + mf * 16 + aRow;
                ldsm4(af[mf], bA + SWZ128(row * 128 + kb + aKx));
            }
            uint32_t bf[2][4];
#pragma unroll
            for (int nf = 0; nf < 2; nf++) {
                int row = nwOff + nf * 16 + bRow;
                ldsm4(bf[nf], bW + SWZ128(row * 128 + kb + bKx));
            }
#pragma unroll
            for (int mf = 0; mf < 2; mf++) {
                mma16816(acc[mf][0], af[mf], &bf[0][0]);
                mma16816(acc[mf][1], af[mf], &bf[0][2]);
                mma16816(acc[mf][2], af[mf], &bf[1][0]);
                mma16816(acc[mf][3], af[mf], &bf[1][2]);
            }
        }
        __syncthreads();
    }

    float* G = (float*)smb;
    {
        const int r0 = lane >> 2, c0 = 2 * (lane & 3);
#pragma unroll
        for (int mf = 0; mf < 2; mf++) {
#pragma unroll
            for (int n8 = 0; n8 < 4; n8++) {
                int row = mwOff + mf * 16 + r0;
                int col = nwOff + n8 * 8 + c0;
                *(float2*)&G[row * GSTRIDE + col]       = make_float2(acc[mf][n8][0], acc[mf][n8][1]);
                *(float2*)&G[(row + 8) * GSTRIDE + col] = make_float2(acc[mf][n8][2], acc[mf][n8][3]);
            }
        }
    }
    __syncthreads();

    const float* bias = g_biasPk + n0;
    float* Hbase = g_H + (size_t)t * BH;
    __half* AbN = g_Ab[(t + 1) & 1];
    const int j0 = nt * 16;
#pragma unroll
    for (int e = 0; e < 8; e++) {
        int cell = e * 128 + tid;
        int m  = cell >> 4;
        int u  = cell & 15;
        int b  = m0 + m;
        int gj = j0 + u;
        float4 gv = *(const float4*)&G[m * GSTRIDE + u * 4];
        float4 bv = *(const float4*)&bias[u * 4];
        float gi = gv.x + bv.x;
        float gf = gv.y + bv.y;
        float gg = gv.z + bv.z;
        float go = gv.w + bv.w;
        int ci = b * HID + gj;
        float c = sigmoidf_(gf) * g_C[ci] + sigmoidf_(gi) * tanhf(gg);
        g_C[ci] = c;
        float h = sigmoidf_(go) * tanhf(c);
        Hbase[ci] = h;
        __half hh = __float2half_rn(h);
        AbN[(size_t)b * 1536 + gj]       = hh;
        AbN[(size_t)b * 1536 + 768 + gj] = __float2half_rn(h - __half2float(hh));
    }
}

// ====================================================================
// Persistent LSTM kernel for t=1..99. Grid (48 nt, 2 mt) = 96 CTAs, 256 thr.
// W slice (64n x 1536k hi+lo = 192KB) loaded ONCE into smem; per step only
// A (=h) streams (24 x 16KB items). Device-wide barrier between steps.
// Epilogue: shfl pair-exchange -> full gate quadruples, no smem regroup.
// ====================================================================
__global__ __launch_bounds__(256) void lstm_persist() {
    extern __shared__ char dyn_raw[];
    char* smb = (char*)(((uintptr_t)dyn_raw + 1023) & ~(uintptr_t)1023);
    char* Wslab = smb;                       // 24 chunks x 8KB
    char* Abuf  = smb + W_SLAB;              // 2 x 16KB

    const int tid  = threadIdx.x;
    const int wid  = tid >> 5;
    const int lane = tid & 31;
    const int nt   = blockIdx.x;
    const int m0   = blockIdx.y * 128;
    const int n0   = nt * 64;

    const uint32_t Wslab32 = smem_u32(Wslab);
    const uint32_t Abuf32  = smem_u32(Abuf);

    // warp tiling: 8 warps -> 4 x 32m, 2 x 32n
    const int mwOff = (wid & 3) * 32;
    const int nwOff = (wid >> 2) * 32;

    // A fill coords (256 thr, 128 rows x 128B per item)
    const int frow = tid >> 3;               // 0..31
    const int fcb  = (tid & 7) * 16;

    // ldmatrix per-lane coords
    const int grp = lane >> 3, lrw = lane & 7;
    const int aRow = ((grp & 1) ? 8 : 0) + lrw;
    const int aKx  = (grp & 2) ? 16 : 0;
    const int bRow = ((grp & 2) ? 8 : 0) + lrw;
    const int bKx  = (grp & 1) ? 16 : 0;

    // ---- one-time W slab load: chunk cw holds k-cols cw*64..+63 (wh: 0..11, wl: 12..23)
#pragma unroll 4
    for (int i = 0; i < 48; i++) {
        int lin = tid + 256 * i;
        int cw  = lin >> 9;                  // /512 (64 rows x 8 units)
        int rem = lin & 511;
        int row = rem >> 3;
        int c16 = rem & 7;
        cp_async16(Wslab32 + cw * 8192 + SWZ128(row * 128 + c16 * 16),
                   (const char*)g_Wr + ((size_t)(n0 + row) * 1536 + cw * 64) * 2 + c16 * 16);
    }
    CP_COMMIT(); CP_WAIT(0);
    __syncthreads();

    for (int t = 1; t < TLEN; t++) {
        const __half* A = g_Ab[t & 1];

        float acc[2][4][4];
#pragma unroll
        for (int a = 0; a < 2; a++)
#pragma unroll
            for (int b = 0; b < 4; b++)
#pragma unroll
                for (int c = 0; c < 4; c++) acc[a][b][c] = 0.0f;

        // item i: even -> ah chunk (i/2) [passes vs wh_c and wl_c]; odd -> al chunk (i/2) [vs wh_c]
        auto fillA = [&](int item) {
            int c = item >> 1;
            int aOff = ((item & 1) ? 768 : 0) + c * 64;
            uint32_t dst = Abuf32 + (item & 1) * A_ITEMB;
#pragma unroll
            for (int i = 0; i < 4; i++) {
                int row = frow + 32 * i;     // 0..127
                cp_async16(dst + SWZ128(row * 128 + fcb),
                           (const char*)A + ((size_t)(m0 + row) * 1536 + aOff) * 2 + fcb);
            }
        };

        auto pass = [&](uint32_t bA, uint32_t bW) {
#pragma unroll
            for (int k16 = 0; k16 < 4; k16++) {
                const int kb = k16 * 32;
                uint32_t af[2][4];
#pragma unroll
                for (int mf = 0; mf < 2; mf++) {
                    int row = mwOff + mf * 16 + aRow;
                    ldsm4(af[mf], bA + SWZ128(row * 128 + kb + aKx));
                }
                uint32_t bf[2][4];
#pragma unroll
                for (int nf = 0; nf < 2; nf++) {
                    int row = nwOff + nf * 16 + bRow;
                    ldsm4(bf[nf], bW + SWZ128(row * 128 + kb + bKx));
                }
#pragma unroll
                for (int mf = 0; mf < 2; mf++) {
                    mma16816(acc[mf][0], af[mf], &bf[0][0]);
                    mma16816(acc[mf][1], af[mf], &bf[0][2]);
                    mma16816(acc[mf][2], af[mf], &bf[1][0]);
                    mma16816(acc[mf][3], af[mf], &bf[1][2]);
                }
            }
        };

        fillA(0); CP_COMMIT();
        for (int it = 0; it < 24; it++) {
            if (it + 1 < 24) { fillA(it + 1); CP_COMMIT(); CP_WAIT(1); }
            else             { CP_WAIT(0); }
            __syncthreads();
            const uint32_t bA = Abuf32 + (it & 1) * A_ITEMB;
            const int c = it >> 1;
            if ((it & 1) == 0) {
                pass(bA, Wslab32 + c * 8192);          // ah_c x wh_c
                pass(bA, Wslab32 + (12 + c) * 8192);   // ah_c x wl_c
            } else {
                pass(bA, Wslab32 + c * 8192);          // al_c x wh_c
            }
            __syncthreads();
        }

        // ---- epilogue: shfl pair-exchange -> gate quadruples, fused pointwise
        {
            const int r0 = lane >> 2;
            const int e  = lane & 1;                  // 0: row r0 cell, 1: row r0+8 cell
            const int q  = ((lane >> 1) & 1) * 4;     // quadruple base within 8-col block
            const float* biasQ = g_biasPk + n0;
            float* Hbase = g_H + (size_t)t * BH;
            __half* AbN = g_Ab[(t + 1) & 1];
#pragma unroll
            for (int mf = 0; mf < 2; mf++) {
#pragma unroll
                for (int n8 = 0; n8 < 4; n8++) {
                    float v0 = acc[mf][n8][0], v1 = acc[mf][n8][1];
                    float v2 = acc[mf][n8][2], v3 = acc[mf][n8][3];
                    float s0 = __shfl_xor_sync(0xffffffffu, v0, 1);
                    float s1 = __shfl_xor_sync(0xffffffffu, v1, 1);
                    float s2 = __shfl_xor_sync(0xffffffffu, v2, 1);
                    float s3 = __shfl_xor_sync(0xffffffffu, v3, 1);
                    float gi = e ? s2 : v0;
                    float gf = e ? s3 : v1;
                    float gg = e ? v2 : s0;
                    float go = e ? v3 : s1;
                    int colbase = nwOff + n8 * 8 + q;
                    int j  = nt * 16 + (colbase >> 2);
                    int m  = m0 + mwOff + mf * 16 + r0 + e * 8;
                    float4 bv = *(const float4*)&biasQ[colbase];
                    gi += bv.x; gf += bv.y; gg += bv.z; go += bv.w;
                    int ci = m * HID + j;
                    float c = sigmoidf_(gf) * g_C[ci] + sigmoidf_(gi) * tanhf(gg);
                    g_C[ci] = c;
                    float h = sigmoidf_(go) * tanhf(c);
                    Hbase[ci] = h;
                    __half hh = __float2half_rn(h);
                    AbN[(size_t)m * 1536 + j]       = hh;
                    AbN[(size_t)m * 1536 + 768 + j] = __float2half_rn(h - __half2float(hh));
                }
            }
        }

        // ---- device-wide barrier (arrive/release, generation = t)
        __syncthreads();
        if (tid == 0) {
            __threadfence();
            unsigned v = atomicAdd(&g_barA, 1u);
            if (v == PNB - 1) {
                g_barA = 0;
                __threadfence();
                g_barR = (unsigned)t;
            } else {
                while (g_barR < (unsigned)t) __nanosleep(64);
            }
            __threadfence();
        }
        __syncthreads();
    }
}

// ====================================================================
// Post projection: out[b][t][o] = H[t][b][:] . W_post[o][:] + b_post[o]
// ====================================================================
__global__ __launch_bounds__(128) void post_proj(const float* __restrict__ Wpost,
                                                 const float* __restrict__ bpost,
                                                 float* __restrict__ out) {
    __shared__ float pA[16][64];
    __shared__ float pW[16][72];

    const int tid = threadIdx.x;
    const int t   = blockIdx.x;
    const int m0  = blockIdx.y * 64;
    const int tm  = tid >> 2;
    const int to  = tid & 3;
    const int m   = 2 * tm;
    const int ob  = 18 * to;
    const int lr  = tid >> 1;
    const int lk  = (tid & 1) * 8;

    const float* __restrict__ Abase = g_H + (size_t)t * BH + (size_t)m0 * HID;

    unsigned long long acc[2][9];
#pragma unroll
    for (int mi = 0; mi < 2; mi++)
#pragma unroll
        for (int oi = 0; oi < 9; oi++) acc[mi][oi] = 0ull;

    for (int kc = 0; kc < HID; kc += 16) {
        float4 v0 = *(const float4*)&Abase[(size_t)lr * HID + kc + lk];
        float4 v1 = *(const float4*)&Abase[(size_t)lr * HID + kc + lk + 4];
        pA[lk + 0][lr] = v0.x; pA[lk + 1][lr] = v0.y;
        pA[lk + 2][lr] = v0.z; pA[lk + 3][lr] = v0.w;
        pA[lk + 4][lr] = v1.x; pA[lk + 5][lr] = v1.y;
        pA[lk + 6][lr] = v1.z; pA[lk + 7][lr] = v1.w;
#pragma unroll
        for (int l = 0; l < 9; l++) {
            int lin = tid + 128 * l;
            int k = lin / 72;
            int o = lin - k * 72;
            pW[k][o] = Wpost[o * HID + kc + k];
        }
        __syncthreads();
#pragma unroll
        for (int k = 0; k < 16; k++) {
            float2 av = *(const float2*)&pA[k][m];
            unsigned long long a0 = pack2(av.x, av.x);
            unsigned long long a1 = pack2(av.y, av.y);
#pragma unroll
            for (int oi = 0; oi < 9; oi++) {
                unsigned long long w = *(const unsigned long long*)&pW[k][ob + 2 * oi];
                fma2(acc[0][oi], a0, w);
                fma2(acc[1][oi], a1, w);
            }
        }
        __syncthreads();
    }
#pragma unroll
    for (int mi = 0; mi < 2; mi++) {
        int b = m0 + m + mi;
        float* orow = out + (size_t)b * (TLEN * OUTD) + t * OUTD;
#pragma unroll
        for (int oi = 0; oi < 9; oi++) {
            float x, y;
            unpack2(acc[mi][oi], x, y);
            int o = ob + 2 * oi;
            orow[o]     = x + bpost[o];
            orow[o + 1] = y + bpost[o + 1];
        }
    }
}

// ====================================================================
// kernel_launch: prep -> t=0 step -> persistent t=1..99 -> projection
// ====================================================================
extern "C" void kernel_launch(void* const* d_in, const int* in_sizes, int n_in,
                              void* d_out, int out_size) {
    const float* src   = (const float*)d_in[0];
    const float* h0    = (const float*)d_in[2];
    const float* c0    = (const float*)d_in[3];
    const float* Wih   = (const float*)d_in[4];
    const float* Whh   = (const float*)d_in[5];
    const float* bih   = (const float*)d_in[6];
    const float* bhh   = (const float*)d_in[7];
    const float* Wpost = (const float*)d_in[8];
    const float* bpost = (const float*)d_in[9];
    float* out = (float*)d_out;

    cudaFuncSetAttribute(lstm_step_mma, cudaFuncAttributeMaxDynamicSharedMemorySize, DYN_SMEM);
    cudaFuncSetAttribute(lstm_persist,  cudaFuncAttributeMaxDynamicSharedMemorySize, P_SMEM);

    prepWr   <<<2048, 256>>>(Wih, Whh);
    prepW0k  <<<2048, 256>>>(Wih, Whh);
    prepState<<<2048, 256>>>(src, h0, c0, bih, bhh);

    dim3 g0(48, 4);
    lstm_step_mma<<<g0, 128, DYN_SMEM>>>(0);

    dim3 gp(48, 2);      // 96 CTAs, 1/SM (230KB smem) -> wave-1 co-resident
    lstm_persist<<<gp, 256, P_SMEM>>>();

    dim3 pgrid(TLEN, 4);
    post_proj<<<pgrid, 128>>>(Wpost, bpost, out);
}

// round 17
// speedup vs baseline: 1.0446x; 1.0446x over previous
#include <cuda_runtime.h>
#include <cuda_fp16.h>
#include <math.h>
#include <stdint.h>

// Problem constants
#define BATCH 256
#define HID   768
#define G4    3072
#define TLEN  100
#define OUTD  72
#define SRCL  16
#define BH    (BATCH * HID)

// t=0 kernel geometry (per-launch, streams W0)
#define STAGE_K   64
#define A_TILEB0  8192
#define W_TILEB0  8192
#define BUFB0     (A_TILEB0 + W_TILEB0)
#define GSTRIDE   68
#define DYN_SMEM0 (1024 + 2 * BUFB0)

// persistent kernel (t=1..99): wh resident, {ah,al,wl} streamed depth-3
#define PNB      96                         // 48 nt x 2 mt CTAs (<=148: wave-1 co-resident)
#define NCHUNK   12                         // 768 k / 64
#define WH_SLAB  (NCHUNK * 8192)            // 96KB resident wh
#define A_ITEMB  16384                      // 128 rows x 128B
#define WL_ITEMB 8192                       // 64 rows x 128B
#define CHUNKB   (2 * A_ITEMB + WL_ITEMB)   // ah + al + wl = 40KB
#define DEPTH    3
#define P_SMEM   (1024 + WH_SLAB + DEPTH * CHUNKB)  // 222208 <= 232448

// -------- device scratch (allocation-free: __device__ globals) --------
static __device__ __half g_Wr [G4 * 1536];      // rec W (Wih+Whh): row n -> [wh(768)|wl(768)]
static __device__ __half g_W0 [G4 * 3072];      // t=0 W [Wih|Whh]: row n -> [w0h|w0l]
static __device__ __half g_A0b[BATCH * 3072];   // [a0h|a0l], a0=[x0|h0]
static __device__ __half g_Ab [2][BATCH * 1536];// h hi/lo ping-pong
static __device__ float g_C[BATCH * HID];
static __device__ float g_H[TLEN * BATCH * HID];
static __device__ float g_biasPk[G4];           // bias, packed n = j*4 + g
static __device__ unsigned g_barA;              // grid barrier arrive counter
static __device__ volatile unsigned g_barR;     // grid barrier release generation

// -------- helpers --------
__device__ __forceinline__ uint32_t smem_u32(const void* p) {
    uint32_t a;
    asm("{ .reg .u64 t; cvta.to.shared.u64 t, %1; cvt.u32.u64 %0, t; }" : "=r"(a) : "l"(p));
    return a;
}
#define SWZ128(o) ((o) ^ (((o) >> 3) & 0x70))

__device__ __forceinline__ float sigmoidf_(float x) { return 1.0f / (1.0f + expf(-x)); }

__device__ __forceinline__ void cp_async16(uint32_t dst, const void* src) {
    asm volatile("cp.async.cg.shared.global [%0], [%1], 16;" :: "r"(dst), "l"(src));
}
#define CP_COMMIT()  asm volatile("cp.async.commit_group;" ::: "memory")
#define CP_WAIT(n)   asm volatile("cp.async.wait_group %0;" :: "n"(n) : "memory")

__device__ __forceinline__ void ldsm4(uint32_t* r, uint32_t addr) {
    asm volatile("ldmatrix.sync.aligned.m8n8.x4.shared.b16 {%0,%1,%2,%3}, [%4];"
                 : "=r"(r[0]), "=r"(r[1]), "=r"(r[2]), "=r"(r[3]) : "r"(addr));
}
__device__ __forceinline__ void mma16816(float* c, const uint32_t* a, const uint32_t* b) {
    asm volatile("mma.sync.aligned.m16n8k16.row.col.f32.f16.f16.f32 "
                 "{%0,%1,%2,%3}, {%4,%5,%6,%7}, {%8,%9}, {%0,%1,%2,%3};"
                 : "+f"(c[0]), "+f"(c[1]), "+f"(c[2]), "+f"(c[3])
                 : "r"(a[0]), "r"(a[1]), "r"(a[2]), "r"(a[3]), "r"(b[0]), "r"(b[1]));
}

// f32x2 helpers (post_proj)
__device__ __forceinline__ unsigned long long pack2(float x, float y) {
    unsigned long long r; asm("mov.b64 %0, {%1, %2};" : "=l"(r) : "f"(x), "f"(y)); return r;
}
__device__ __forceinline__ void unpack2(unsigned long long v, float& x, float& y) {
    asm("mov.b64 {%0, %1}, %2;" : "=f"(x), "=f"(y) : "l"(v));
}
__device__ __forceinline__ void fma2(unsigned long long& d, unsigned long long a, unsigned long long b) {
    asm("fma.rn.f32x2 %0, %1, %2, %0;" : "+l"(d) : "l"(a), "l"(b));
}

// packed-N index n = j*4 + g -> original weight row g*768 + j
__device__ __forceinline__ int rowFromN(int n) {
    return (n & 3) * HID + (n >> 2);
}

// ====================================================================
// Prep kernels
// ====================================================================
__global__ void prepWr(const float* __restrict__ Wih, const float* __restrict__ Whh) {
    const int stride = gridDim.x * blockDim.x;
    for (int idx = blockIdx.x * blockDim.x + threadIdx.x; idx < G4 * HID; idx += stride) {
        int n = idx / HID, k = idx - n * HID;
        int row = rowFromN(n);
        float w = Wih[row * HID + k] + Whh[row * HID + k];
        __half wh = __float2half_rn(w);
        g_Wr[n * 1536 + k]       = wh;
        g_Wr[n * 1536 + 768 + k] = __float2half_rn(w - __half2float(wh));
    }
}
__global__ void prepW0k(const float* __restrict__ Wih, const float* __restrict__ Whh) {
    const int stride = gridDim.x * blockDim.x;
    for (int idx = blockIdx.x * blockDim.x + threadIdx.x; idx < G4 * 1536; idx += stride) {
        int n = idx / 1536, k = idx - n * 1536;
        int row = rowFromN(n);
        float w = (k < HID) ? Wih[row * HID + k] : Whh[row * HID + (k - HID)];
        __half wh = __float2half_rn(w);
        g_W0[n * 3072 + k]        = wh;
        g_W0[n * 3072 + 1536 + k] = __float2half_rn(w - __half2float(wh));
    }
}
__global__ void prepState(const float* __restrict__ src, const float* __restrict__ h0,
                          const float* __restrict__ c0, const float* __restrict__ bih,
                          const float* __restrict__ bhh) {
    const int stride = gridDim.x * blockDim.x;
    const int t0 = blockIdx.x * blockDim.x + threadIdx.x;
    if (t0 == 0) { g_barA = 0; g_barR = 0; }     // reset grid barrier each replay
    for (int idx = t0; idx < BATCH * 1536; idx += stride) {
        int m = idx / 1536, q = idx - m * 1536;
        float a = (q < HID) ? src[(m * SRCL + (SRCL - 1)) * HID + q] : h0[m * HID + (q - HID)];
        __half ah = __float2half_rn(a);
        g_A0b[m * 3072 + q]        = ah;
        g_A0b[m * 3072 + 1536 + q] = __float2half_rn(a - __half2float(ah));
    }
    for (int idx = t0; idx < BATCH * HID; idx += stride) g_C[idx] = c0[idx];
    for (int idx = t0; idx < G4; idx += stride) {
        int row = rowFromN(idx);
        g_biasPk[idx] = bih[row] + bhh[row];
    }
}

// ====================================================================
// t=0 LSTM step (per-launch; streams W0). Grid (48,4), 128 thr. (validated)
// ====================================================================
__global__ __launch_bounds__(128) void lstm_step_mma(int t) {
    extern __shared__ char dyn_raw[];
    char* smb = (char*)(((uintptr_t)dyn_raw + 1023) & ~(uintptr_t)1023);

    const int tid  = threadIdx.x;
    const int wid  = tid >> 5;
    const int lane = tid & 31;
    const int nt   = blockIdx.x;
    const int m0   = blockIdx.y * 64;
    const int n0   = nt * 64;

    const __half* Aglob = g_A0b;
    const __half* Wglob = g_W0;
    const int kBase = 1536;
    const int rowStride = 2 * kBase;
    const int nStages   = (3 * kBase) / STAGE_K;

    const int mwOff = (wid & 1) * 32;
    const int nwOff = (wid >> 1) * 32;
    const int frow = tid >> 3;
    const int fcb  = (tid & 7) * 16;
    const int grp = lane >> 3, lrw = lane & 7;
    const int aRow = ((grp & 1) ? 8 : 0) + lrw;
    const int aKx  = (grp & 2) ? 16 : 0;
    const int bRow = ((grp & 2) ? 8 : 0) + lrw;
    const int bKx  = (grp & 1) ? 16 : 0;

    const uint32_t smb32 = smem_u32(smb);

    float acc[2][4][4];
#pragma unroll
    for (int a = 0; a < 2; a++)
#pragma unroll
        for (int b = 0; b < 4; b++)
#pragma unroll
            for (int c = 0; c < 4; c++) acc[a][b][c] = 0.0f;

    auto fill = [&](int s) {
        const int b = s & 1;
        const uint32_t dA = smb32 + b * BUFB0;
        const uint32_t dW = dA + A_TILEB0;
        const int segBase = s * STAGE_K;
        const int seg = segBase / kBase;
        const int kk  = segBase - seg * kBase;
        const int aOff = (seg == 1) ? kBase + kk : kk;
        const int wOff = (seg == 2) ? kBase + kk : kk;
#pragma unroll
        for (int i = 0; i < 4; i++) {
            int row = frow + 16 * i;
            cp_async16(dA + SWZ128(row * 128 + fcb),
                       (const char*)Aglob + ((size_t)(m0 + row) * rowStride + aOff) * 2 + fcb);
        }
#pragma unroll
        for (int i = 0; i < 4; i++) {
            int row = frow + 16 * i;
            cp_async16(dW + SWZ128(row * 128 + fcb),
                       (const char*)Wglob + ((size_t)(n0 + row) * rowStride + wOff) * 2 + fcb);
        }
    };

    fill(0); CP_COMMIT();

    for (int s = 0; s < nStages; s++) {
        if (s + 1 < nStages) { fill(s + 1); CP_COMMIT(); CP_WAIT(1); }
        else                 { CP_WAIT(0); }
        __syncthreads();

        const uint32_t bA = smb32 + (s & 1) * BUFB0;
        const uint32_t bW = bA + A_TILEB0;
#pragma unroll
        for (int k16 = 0; k16 < 4; k16++) {
            const int kb = k16 * 32;
            uint32_t af[2][4];
#pragma unroll
            for (int mf = 0; mf < 2; mf++) {
                int row = mwOff + mf * 16 + aRow;
                ldsm4(af[mf], bA + SWZ128(row * 128 + kb + aKx));
            }
            uint32_t bf[2][4];
#pragma unroll
            for (int nf = 0; nf < 2; nf++) {
                int row = nwOff + nf * 16 + bRow;
                ldsm4(bf[nf], bW + SWZ128(row * 128 + kb + bKx));
            }
#pragma unroll
            for (int mf = 0; mf < 2; mf++) {
                mma16816(acc[mf][0], af[mf], &bf[0][0]);
                mma16816(acc[mf][1], af[mf], &bf[0][2]);
                mma16816(acc[mf][2], af[mf], &bf[1][0]);
                mma16816(acc[mf][3], af[mf], &bf[1][2]);
            }
        }
        __syncthreads();
    }

    float* G = (float*)smb;
    {
        const int r0 = lane >> 2, c0 = 2 * (lane & 3);
#pragma unroll
        for (int mf = 0; mf < 2; mf++) {
#pragma unroll
            for (int n8 = 0; n8 < 4; n8++) {
                int row = mwOff + mf * 16 + r0;
                int col = nwOff + n8 * 8 + c0;
                *(float2*)&G[row * GSTRIDE + col]       = make_float2(acc[mf][n8][0], acc[mf][n8][1]);
                *(float2*)&G[(row + 8) * GSTRIDE + col] = make_float2(acc[mf][n8][2], acc[mf][n8][3]);
            }
        }
    }
    __syncthreads();

    const float* bias = g_biasPk + n0;
    float* Hbase = g_H + (size_t)t * BH;
    __half* AbN = g_Ab[(t + 1) & 1];
    const int j0 = nt * 16;
#pragma unroll
    for (int e = 0; e < 8; e++) {
        int cell = e * 128 + tid;
        int m  = cell >> 4;
        int u  = cell & 15;
        int b  = m0 + m;
        int gj = j0 + u;
        float4 gv = *(const float4*)&G[m * GSTRIDE + u * 4];
        float4 bv = *(const float4*)&bias[u * 4];
        float gi = gv.x + bv.x;
        float gf = gv.y + bv.y;
        float gg = gv.z + bv.z;
        float go = gv.w + bv.w;
        int ci = b * HID + gj;
        float c = sigmoidf_(gf) * g_C[ci] + sigmoidf_(gi) * tanhf(gg);
        g_C[ci] = c;
        float h = sigmoidf_(go) * tanhf(c);
        Hbase[ci] = h;
        __half hh = __float2half_rn(h);
        AbN[(size_t)b * 1536 + gj]       = hh;
        AbN[(size_t)b * 1536 + 768 + gj] = __float2half_rn(h - __half2float(hh));
    }
}

// ====================================================================
// Persistent LSTM kernel, t=1..99. Grid (48 nt, 2 mt) = 96 CTAs, 256 thr.
// wh (64n x 768k = 96KB) resident; per chunk c stream {ah_c, al_c, wl_c}
// (40KB) through a DEPTH-3 ring -> fills issued 2 chunks ahead, ONE
// __syncthreads per chunk (12/step vs R15's 48).
// Passes per chunk: ah*wh (resident), al*wh (resident), ah*wl (streamed).
// ====================================================================
__global__ __launch_bounds__(256) void lstm_persist() {
    extern __shared__ char dyn_raw[];
    char* smb   = (char*)(((uintptr_t)dyn_raw + 1023) & ~(uintptr_t)1023);
    char* WhS   = smb;                       // 12 x 8KB resident wh
    char* Ring  = smb + WH_SLAB;             // DEPTH x 40KB {ah, al, wl}

    const int tid  = threadIdx.x;
    const int wid  = tid >> 5;
    const int lane = tid & 31;
    const int nt   = blockIdx.x;
    const int m0   = blockIdx.y * 128;
    const int n0   = nt * 64;

    const uint32_t Wh32   = smem_u32(WhS);
    const uint32_t Ring32 = smem_u32(Ring);

    // 8 warps -> 4 x 32m, 2 x 32n
    const int mwOff = (wid & 3) * 32;
    const int nwOff = (wid >> 2) * 32;

    const int frow = tid >> 3;               // 0..31
    const int fcb  = (tid & 7) * 16;

    const int grp = lane >> 3, lrw = lane & 7;
    const int aRow = ((grp & 1) ? 8 : 0) + lrw;
    const int aKx  = (grp & 2) ? 16 : 0;
    const int bRow = ((grp & 2) ? 8 : 0) + lrw;
    const int bKx  = (grp & 1) ? 16 : 0;

    // ---- one-time resident wh load (12 chunks x 64 rows x 128B)
#pragma unroll 4
    for (int i = 0; i < 24; i++) {
        int lin = tid + 256 * i;             // 0..6143
        int cw  = lin >> 9;
        int rem = lin & 511;
        int row = rem >> 3;
        int c16 = rem & 7;
        cp_async16(Wh32 + cw * 8192 + SWZ128(row * 128 + c16 * 16),
                   (const char*)g_Wr + ((size_t)(n0 + row) * 1536 + cw * 64) * 2 + c16 * 16);
    }
    CP_COMMIT(); CP_WAIT(0);
    __syncthreads();

    for (int t = 1; t < TLEN; t++) {
        const __half* A = g_Ab[t & 1];

        float acc[2][4][4];
#pragma unroll
        for (int a = 0; a < 2; a++)
#pragma unroll
            for (int b = 0; b < 4; b++)
#pragma unroll
                for (int c = 0; c < 4; c++) acc[a][b][c] = 0.0f;

        // fill chunk c into ring slot c%DEPTH: ah (4/thr), al (4/thr), wl (2/thr)
        auto fillC = [&](int c) {
            uint32_t dst = Ring32 + (c % DEPTH) * CHUNKB;
            const char* ahSrc = (const char*)A;
#pragma unroll
            for (int i = 0; i < 4; i++) {
                int row = frow + 32 * i;
                cp_async16(dst + SWZ128(row * 128 + fcb),
                           ahSrc + ((size_t)(m0 + row) * 1536 + c * 64) * 2 + fcb);
            }
#pragma unroll
            for (int i = 0; i < 4; i++) {
                int row = frow + 32 * i;
                cp_async16(dst + A_ITEMB + SWZ128(row * 128 + fcb),
                           ahSrc + ((size_t)(m0 + row) * 1536 + 768 + c * 64) * 2 + fcb);
            }
#pragma unroll
            for (int i = 0; i < 2; i++) {
                int lin = tid + 256 * i;     // 0..511
                int row = lin >> 3;
                int c16 = (lin & 7) * 16;
                cp_async16(dst + 2 * A_ITEMB + SWZ128(row * 128 + c16),
                           (const char*)g_Wr + ((size_t)(n0 + row) * 1536 + 768 + c * 64) * 2 + c16);
            }
        };

        auto pass = [&](uint32_t bA, uint32_t bW) {
#pragma unroll
            for (int k16 = 0; k16 < 4; k16++) {
                const int kb = k16 * 32;
                uint32_t af[2][4];
#pragma unroll
                for (int mf = 0; mf < 2; mf++) {
                    int row = mwOff + mf * 16 + aRow;
                    ldsm4(af[mf], bA + SWZ128(row * 128 + kb + aKx));
                }
                uint32_t bf[2][4];
#pragma unroll
                for (int nf = 0; nf < 2; nf++) {
                    int row = nwOff + nf * 16 + bRow;
                    ldsm4(bf[nf], bW + SWZ128(row * 128 + kb + bKx));
                }
#pragma unroll
                for (int mf = 0; mf < 2; mf++) {
                    mma16816(acc[mf][0], af[mf], &bf[0][0]);
                    mma16816(acc[mf][1], af[mf], &bf[0][2]);
                    mma16816(acc[mf][2], af[mf], &bf[1][0]);
                    mma16816(acc[mf][3], af[mf], &bf[1][2]);
                }
            }
        };

        // prologue: 2 chunks in flight
        fillC(0); CP_COMMIT();
        fillC(1); CP_COMMIT();

        for (int c = 0; c < NCHUNK; c++) {
            if (c + 1 < NCHUNK) CP_WAIT(1);   // chunk c complete (c+1 may fly)
            else                CP_WAIT(0);
            __syncthreads();                  // all warps past chunk c-1 compute
            if (c + 2 < NCHUNK) { fillC(c + 2); CP_COMMIT(); }  // slot (c-1)%D now free

            const uint32_t buf = Ring32 + (c % DEPTH) * CHUNKB;
            const uint32_t wh  = Wh32 + c * 8192;
            pass(buf,            wh);               // ah_c x wh_c
            pass(buf + A_ITEMB,  wh);               // al_c x wh_c
            pass(buf,            buf + 2 * A_ITEMB);// ah_c x wl_c
        }

        // ---- epilogue: shfl pair-exchange -> gate quadruples, fused pointwise
        {
            const int r0 = lane >> 2;
            const int e  = lane & 1;
            const int q  = ((lane >> 1) & 1) * 4;
            const float* biasQ = g_biasPk + n0;
            float* Hbase = g_H + (size_t)t * BH;
            __half* AbN = g_Ab[(t + 1) & 1];
#pragma unroll
            for (int mf = 0; mf < 2; mf++) {
#pragma unroll
                for (int n8 = 0; n8 < 4; n8++) {
                    float v0 = acc[mf][n8][0], v1 = acc[mf][n8][1];
                    float v2 = acc[mf][n8][2], v3 = acc[mf][n8][3];
                    float s0 = __shfl_xor_sync(0xffffffffu, v0, 1);
                    float s1 = __shfl_xor_sync(0xffffffffu, v1, 1);
                    float s2 = __shfl_xor_sync(0xffffffffu, v2, 1);
                    float s3 = __shfl_xor_sync(0xffffffffu, v3, 1);
                    float gi = e ? s2 : v0;
                    float gf = e ? s3 : v1;
                    float gg = e ? v2 : s0;
                    float go = e ? v3 : s1;
                    int colbase = nwOff + n8 * 8 + q;
                    int j  = nt * 16 + (colbase >> 2);
                    int m  = m0 + mwOff + mf * 16 + r0 + e * 8;
                    float4 bv = *(const float4*)&biasQ[colbase];
                    gi += bv.x; gf += bv.y; gg += bv.z; go += bv.w;
                    int ci = m * HID + j;
                    float c = sigmoidf_(gf) * g_C[ci] + sigmoidf_(gi) * tanhf(gg);
                    g_C[ci] = c;
                    float h = sigmoidf_(go) * tanhf(c);
                    Hbase[ci] = h;
                    __half hh = __float2half_rn(h);
                    AbN[(size_t)m * 1536 + j]       = hh;
                    AbN[(size_t)m * 1536 + 768 + j] = __float2half_rn(h - __half2float(hh));
                }
            }
        }

        // ---- device-wide barrier (arrive/release, generation = t)
        __syncthreads();
        if (tid == 0) {
            __threadfence();
            unsigned v = atomicAdd(&g_barA, 1u);
            if (v == PNB - 1) {
                g_barA = 0;
                __threadfence();
                g_barR = (unsigned)t;
            } else {
                while (g_barR < (unsigned)t) __nanosleep(64);
            }
            __threadfence();
        }
        __syncthreads();
    }
}

// ====================================================================
// Post projection: out[b][t][o] = H[t][b][:] . W_post[o][:] + b_post[o]
// ====================================================================
__global__ __launch_bounds__(128) void post_proj(const float* __restrict__ Wpost,
                                                 const float* __restrict__ bpost,
                                                 float* __restrict__ out) {
    __shared__ float pA[16][64];
    __shared__ float pW[16][72];

    const int tid = threadIdx.x;
    const int t   = blockIdx.x;
    const int m0  = blockIdx.y * 64;
    const int tm  = tid >> 2;
    const int to  = tid & 3;
    const int m   = 2 * tm;
    const int ob  = 18 * to;
    const int lr  = tid >> 1;
    const int lk  = (tid & 1) * 8;

    const float* __restrict__ Abase = g_H + (size_t)t * BH + (size_t)m0 * HID;

    unsigned long long acc[2][9];
#pragma unroll
    for (int mi = 0; mi < 2; mi++)
#pragma unroll
        for (int oi = 0; oi < 9; oi++) acc[mi][oi] = 0ull;

    for (int kc = 0; kc < HID; kc += 16) {
        float4 v0 = *(const float4*)&Abase[(size_t)lr * HID + kc + lk];
        float4 v1 = *(const float4*)&Abase[(size_t)lr * HID + kc + lk + 4];
        pA[lk + 0][lr] = v0.x; pA[lk + 1][lr] = v0.y;
        pA[lk + 2][lr] = v0.z; pA[lk + 3][lr] = v0.w;
        pA[lk + 4][lr] = v1.x; pA[lk + 5][lr] = v1.y;
        pA[lk + 6][lr] = v1.z; pA[lk + 7][lr] = v1.w;
#pragma unroll
        for (int l = 0; l < 9; l++) {
            int lin = tid + 128 * l;
            int k = lin / 72;
            int o = lin - k * 72;
            pW[k][o] = Wpost[o * HID + kc + k];
        }
        __syncthreads();
#pragma unroll
        for (int k = 0; k < 16; k++) {
            float2 av = *(const float2*)&pA[k][m];
            unsigned long long a0 = pack2(av.x, av.x);
            unsigned long long a1 = pack2(av.y, av.y);
#pragma unroll
            for (int oi = 0; oi < 9; oi++) {
                unsigned long long w = *(const unsigned long long*)&pW[k][ob + 2 * oi];
                fma2(acc[0][oi], a0, w);
                fma2(acc[1][oi], a1, w);
            }
        }
        __syncthreads();
    }
#pragma unroll
    for (int mi = 0; mi < 2; mi++) {
        int b = m0 + m + mi;
        float* orow = out + (size_t)b * (TLEN * OUTD) + t * OUTD;
#pragma unroll
        for (int oi = 0; oi < 9; oi++) {
            float x, y;
            unpack2(acc[mi][oi], x, y);
            int o = ob + 2 * oi;
            orow[o]     = x + bpost[o];
            orow[o + 1] = y + bpost[o + 1];
        }
    }
}

// ====================================================================
// kernel_launch: prep -> t=0 step -> persistent t=1..99 -> projection
// ====================================================================
extern "C" void kernel_launch(void* const* d_in, const int* in_sizes, int n_in,
                              void* d_out, int out_size) {
    const float* src   = (const float*)d_in[0];
    const float* h0    = (const float*)d_in[2];
    const float* c0    = (const float*)d_in[3];
    const float* Wih   = (const float*)d_in[4];
    const float* Whh   = (const float*)d_in[5];
    const float* bih   = (const float*)d_in[6];
    const float* bhh   = (const float*)d_in[7];
    const float* Wpost = (const float*)d_in[8];
    const float* bpost = (const float*)d_in[9];
    float* out = (float*)d_out;

    cudaFuncSetAttribute(lstm_step_mma, cudaFuncAttributeMaxDynamicSharedMemorySize, DYN_SMEM0);
    cudaFuncSetAttribute(lstm_persist,  cudaFuncAttributeMaxDynamicSharedMemorySize, P_SMEM);

    prepWr   <<<2048, 256>>>(Wih, Whh);
    prepW0k  <<<2048, 256>>>(Wih, Whh);
    prepState<<<2048, 256>>>(src, h0, c0, bih, bhh);

    dim3 g0(48, 4);
    lstm_step_mma<<<g0, 128, DYN_SMEM0>>>(0);

    dim3 gp(48, 2);      // 96 CTAs, 1/SM -> wave-1 co-resident (grid barrier safe)
    lstm_persist<<<gp, 256, P_SMEM>>>();

    dim3 pgrid(TLEN, 4);
    post_proj<<<pgrid, 128>>>(Wpost, bpost, out);
}